// round 7
// baseline (speedup 1.0000x reference)
#include <cuda_runtime.h>
#include <cuda_bf16.h>

#define N_NODES 100000
#define N_EDGES 3200000
#define F_IN 8
#define F_HID 64
#define SCAN_B 256
#define NB_SCAN ((N_NODES + SCAN_B - 1) / SCAN_B)   // 391

// Scratch: __device__ globals (GPU DRAM; allocation-free rule)
__device__ float g_deg[N_NODES];
__device__ float g_dinv[N_NODES];
__device__ __align__(16) float g_xs[N_NODES * F_IN];     // dinv[i]*x[i]
__device__ __align__(16) float g_acc1[N_NODES * F_IN];   // layer-1 neighbor sums
__device__ float g_sd[N_NODES];                          // dinv[i]*s[i]
__device__ int   g_cnt[N_NODES];                         // in-degree (edge count)
__device__ int   g_off[N_NODES];                         // CSR segment starts
__device__ int   g_pos[N_EDGES];                         // slot of edge within its segment
__device__ int2  g_csr[N_EDGES];                         // packed (row, weight-bits)
__device__ int   g_partial[NB_SCAN];
__device__ int   g_partial_off[NB_SCAN];

// 1) init: deg=1 (self-loop), cnt=0
__global__ void k_init() {
    int i = blockIdx.x * blockDim.x + threadIdx.x;
    if (i < N_NODES) { g_deg[i] = 1.0f; g_cnt[i] = 0; }
}

// 2) histogram + weighted degree: deg[c]+=w ; pos[e]=cnt[c]++
__global__ void k_hist(const int* __restrict__ ei, const float* __restrict__ w) {
    int e = blockIdx.x * blockDim.x + threadIdx.x;
    if (e >= N_EDGES) return;
    int c = ei[N_EDGES + e];
    atomicAdd(&g_deg[c], w[e]);
    g_pos[e] = atomicAdd(&g_cnt[c], 1);
}

// 3a) per-block sums of cnt
__global__ void k_scan1() {
    __shared__ int sh[SCAN_B];
    int i = blockIdx.x * SCAN_B + threadIdx.x;
    sh[threadIdx.x] = (i < N_NODES) ? g_cnt[i] : 0;
    __syncthreads();
    for (int d = SCAN_B / 2; d > 0; d >>= 1) {
        if (threadIdx.x < d) sh[threadIdx.x] += sh[threadIdx.x + d];
        __syncthreads();
    }
    if (threadIdx.x == 0) g_partial[blockIdx.x] = sh[0];
}

// 3b) exclusive scan of block partials (single block, 512 threads >= NB_SCAN)
__global__ void k_scan2() {
    __shared__ int sh[512];
    int t = threadIdx.x;
    int v = (t < NB_SCAN) ? g_partial[t] : 0;
    sh[t] = v;
    __syncthreads();
    for (int d = 1; d < 512; d <<= 1) {
        int add = (t >= d) ? sh[t - d] : 0;
        __syncthreads();
        sh[t] += add;
        __syncthreads();
    }
    if (t < NB_SCAN) g_partial_off[t] = sh[t] - v;   // exclusive
}

// 3c) block-local exclusive scan + partial offset -> g_off
__global__ void k_scan3() {
    __shared__ int sh[SCAN_B];
    int i = blockIdx.x * SCAN_B + threadIdx.x;
    int v = (i < N_NODES) ? g_cnt[i] : 0;
    sh[threadIdx.x] = v;
    __syncthreads();
    for (int d = 1; d < SCAN_B; d <<= 1) {
        int add = (threadIdx.x >= d) ? sh[threadIdx.x - d] : 0;
        __syncthreads();
        sh[threadIdx.x] += add;
        __syncthreads();
    }
    if (i < N_NODES) g_off[i] = sh[threadIdx.x] - v + g_partial_off[blockIdx.x];
}

// 4) dinv = rsqrt(deg); xs = dinv*x
__global__ void k_dinv_xs(const float* __restrict__ x) {
    int i = blockIdx.x * blockDim.x + threadIdx.x;
    if (i >= N_NODES) return;
    float dv = rsqrtf(g_deg[i]);
    g_dinv[i] = dv;
    const float4* xr = (const float4*)(x + (size_t)i * F_IN);
    float4 a = xr[0], b = xr[1];
    float4* o = (float4*)(g_xs + (size_t)i * F_IN);
    o[0] = make_float4(a.x * dv, a.y * dv, a.z * dv, a.w * dv);
    o[1] = make_float4(b.x * dv, b.y * dv, b.z * dv, b.w * dv);
}

// 5) scatter edges into CSR slots (no atomics)
__global__ void k_scatter(const int* __restrict__ ei, const float* __restrict__ w) {
    int e = blockIdx.x * blockDim.x + threadIdx.x;
    if (e >= N_EDGES) return;
    int r = ei[e];
    int c = ei[N_EDGES + e];
    g_csr[g_off[c] + g_pos[e]] = make_int2(r, __float_as_int(w[e]));
}

// 6) layer-1 aggregation: warp per node, gather+reduce, plain store
__global__ void k_agg1() {
    int gt = blockIdx.x * blockDim.x + threadIdx.x;
    int node = gt >> 5;
    int lane = gt & 31;
    if (node >= N_NODES) return;
    int start = g_off[node];
    int end = start + g_cnt[node];
    float a0=0,a1=0,a2=0,a3=0,a4=0,a5=0,a6=0,a7=0;
    for (int i = start + lane; i < end; i += 32) {
        int2 rec = g_csr[i];
        float we = __int_as_float(rec.y);
        const float4* xr = (const float4*)(g_xs + (size_t)rec.x * F_IN);
        float4 p = xr[0], q = xr[1];
        a0 += we * p.x; a1 += we * p.y; a2 += we * p.z; a3 += we * p.w;
        a4 += we * q.x; a5 += we * q.y; a6 += we * q.z; a7 += we * q.w;
    }
    #pragma unroll
    for (int o = 16; o > 0; o >>= 1) {
        a0 += __shfl_down_sync(0xffffffffu, a0, o);
        a1 += __shfl_down_sync(0xffffffffu, a1, o);
        a2 += __shfl_down_sync(0xffffffffu, a2, o);
        a3 += __shfl_down_sync(0xffffffffu, a3, o);
        a4 += __shfl_down_sync(0xffffffffu, a4, o);
        a5 += __shfl_down_sync(0xffffffffu, a5, o);
        a6 += __shfl_down_sync(0xffffffffu, a6, o);
        a7 += __shfl_down_sync(0xffffffffu, a7, o);
    }
    if (lane == 0) {
        float4* dst = (float4*)(g_acc1 + (size_t)node * F_IN);
        dst[0] = make_float4(a0, a1, a2, a3);
        dst[1] = make_float4(a4, a5, a6, a7);
    }
}

// 7) node MLP: a = dinv*acc1 + dinv^2*x ; s = relu(a@W1+b1)@W2 ; sd = dinv*s
__global__ void k_node_mlp(const float* __restrict__ x,
                           const float* __restrict__ W1,
                           const float* __restrict__ b1,
                           const float* __restrict__ W2) {
    __shared__ float sW1[F_IN * F_HID];
    __shared__ float sb1[F_HID];
    __shared__ float sW2[F_HID];
    for (int t = threadIdx.x; t < F_IN * F_HID; t += blockDim.x) sW1[t] = W1[t];
    for (int t = threadIdx.x; t < F_HID; t += blockDim.x) { sb1[t] = b1[t]; sW2[t] = W2[t]; }
    __syncthreads();

    int i = blockIdx.x * blockDim.x + threadIdx.x;
    if (i >= N_NODES) return;

    float dv = g_dinv[i];
    float dv2 = dv * dv;
    const float4* ac = (const float4*)(g_acc1 + (size_t)i * F_IN);
    const float4* xr = (const float4*)(x + (size_t)i * F_IN);
    float4 A0 = ac[0], A1 = ac[1], X0 = xr[0], X1 = xr[1];
    float a[F_IN];
    a[0] = dv * A0.x + dv2 * X0.x;  a[1] = dv * A0.y + dv2 * X0.y;
    a[2] = dv * A0.z + dv2 * X0.z;  a[3] = dv * A0.w + dv2 * X0.w;
    a[4] = dv * A1.x + dv2 * X1.x;  a[5] = dv * A1.y + dv2 * X1.y;
    a[6] = dv * A1.z + dv2 * X1.z;  a[7] = dv * A1.w + dv2 * X1.w;

    float s = 0.0f;
    #pragma unroll 8
    for (int f = 0; f < F_HID; f++) {
        float acc = sb1[f];
        #pragma unroll
        for (int k = 0; k < F_IN; k++) acc = fmaf(a[k], sW1[k * F_HID + f], acc);
        s += fmaxf(acc, 0.0f) * sW2[f];
    }
    g_sd[i] = dv * s;
}

// 8) layer-2 aggregation + output epilogue: warp per node, no atomics
__global__ void k_agg2out(const float* __restrict__ b2, float* __restrict__ out) {
    int gt = blockIdx.x * blockDim.x + threadIdx.x;
    int node = gt >> 5;
    int lane = gt & 31;
    if (node >= N_NODES) return;
    int start = g_off[node];
    int end = start + g_cnt[node];
    float s = 0.0f;
    for (int i = start + lane; i < end; i += 32) {
        int2 rec = g_csr[i];
        s += __int_as_float(rec.y) * g_sd[rec.x];
    }
    #pragma unroll
    for (int o = 16; o > 0; o >>= 1) s += __shfl_down_sync(0xffffffffu, s, o);
    if (lane == 0) out[node] = b2[0] + g_dinv[node] * (s + g_sd[node]);
}

extern "C" void kernel_launch(void* const* d_in, const int* in_sizes, int n_in,
                              void* d_out, int out_size) {
    const float* x  = (const float*)d_in[0];
    const int*   ei = (const int*)d_in[1];     // int32 (JAX x64 disabled)
    const float* w  = (const float*)d_in[2];
    const float* W1 = (const float*)d_in[3];
    const float* b1 = (const float*)d_in[4];
    const float* W2 = (const float*)d_in[5];
    const float* b2 = (const float*)d_in[6];
    float* out = (float*)d_out;

    const int TB = 256;
    const int gridN = (N_NODES + TB - 1) / TB;
    const int gridE = (N_EDGES + TB - 1) / TB;
    const int gridW = (N_NODES * 32 + TB - 1) / TB;   // warp-per-node kernels

    k_init<<<gridN, TB>>>();
    k_hist<<<gridE, TB>>>(ei, w);
    k_scan1<<<NB_SCAN, SCAN_B>>>();
    k_scan2<<<1, 512>>>();
    k_scan3<<<NB_SCAN, SCAN_B>>>();
    k_dinv_xs<<<gridN, TB>>>(x);
    k_scatter<<<gridE, TB>>>(ei, w);
    k_agg1<<<gridW, TB>>>();
    k_node_mlp<<<gridN, TB>>>(x, W1, b1, W2);
    k_agg2out<<<gridW, TB>>>(b2, out);
}

// round 8
// speedup vs baseline: 1.4881x; 1.4881x over previous
#include <cuda_runtime.h>
#include <cuda_bf16.h>

#define N_NODES 100000
#define N_EDGES 3200000
#define F_IN 8
#define F_HID 64

// Scratch: __device__ globals (GPU DRAM; allocation-free rule)
__device__ float g_deg[N_NODES];                         // accumulated WITHOUT self-loop
__device__ float g_dinv[N_NODES];
__device__ __align__(16) float g_xs[N_NODES * F_IN];     // dinv[i] * x[i]
__device__ __align__(16) float g_acc1[N_NODES * F_IN];   // sum_{edges into c} w * xs[r]
__device__ float g_sd[N_NODES];                          // dinv[i] * s[i]
__device__ float g_acc2[N_NODES];                        // sum_{edges into c} w * sd[r]

// ---------------------------------------------------------------------------
// 1) deg accumulate: deg[col] += w   (deg zeroed by memset; self-loop +1 in dinv)
__global__ void k_deg_acc(const int* __restrict__ ei, const float* __restrict__ w) {
    int e = blockIdx.x * blockDim.x + threadIdx.x;
    if (e >= N_EDGES) return;
    atomicAdd(&g_deg[ei[N_EDGES + e]], w[e]);
}

// 2) dinv = rsqrt(1 + deg); xs = dinv*x; zero acc1 & acc2 (fused init)
__global__ void k_dinv_xs(const float* __restrict__ x) {
    int i = blockIdx.x * blockDim.x + threadIdx.x;
    if (i >= N_NODES) return;
    float dv = rsqrtf(1.0f + g_deg[i]);     // +1 = self-loop weight
    g_dinv[i] = dv;
    const float4* xr = (const float4*)(x + (size_t)i * F_IN);
    float4 a = xr[0], b = xr[1];
    float4* o = (float4*)(g_xs + (size_t)i * F_IN);
    o[0] = make_float4(a.x * dv, a.y * dv, a.z * dv, a.w * dv);
    o[1] = make_float4(b.x * dv, b.y * dv, b.z * dv, b.w * dv);
    float4 z = make_float4(0.f, 0.f, 0.f, 0.f);
    float4* ac = (float4*)(g_acc1 + (size_t)i * F_IN);
    ac[0] = z; ac[1] = z;
    g_acc2[i] = 0.0f;
}

// vectorized fire-and-forget float4 reduction (sm_103a)
__device__ __forceinline__ void red_add_v4(float* p, float a, float b, float c, float d) {
    asm volatile("red.global.add.v4.f32 [%0], {%1,%2,%3,%4};"
                 :: "l"(p), "f"(a), "f"(b), "f"(c), "f"(d) : "memory");
}

// 3) layer-1 edge pass, 1 edge/thread: acc1[c] += w * xs[r]
__global__ void k_layer1_edges(const int* __restrict__ ei, const float* __restrict__ w) {
    int e = blockIdx.x * blockDim.x + threadIdx.x;
    if (e >= N_EDGES) return;
    int r = ei[e];
    int c = ei[N_EDGES + e];
    float we = w[e];
    const float4* xr = (const float4*)(g_xs + (size_t)r * F_IN);
    float4 a = __ldg(xr);
    float4 b = __ldg(xr + 1);
    float* dst = g_acc1 + (size_t)c * F_IN;
    red_add_v4(dst,     we * a.x, we * a.y, we * a.z, we * a.w);
    red_add_v4(dst + 4, we * b.x, we * b.y, we * b.z, we * b.w);
}

// 4) node MLP: a = dinv*acc1 + dinv^2*x ; s = relu(a@W1+b1)@W2 ; sd = dinv*s
__global__ void k_node_mlp(const float* __restrict__ x,
                           const float* __restrict__ W1,
                           const float* __restrict__ b1,
                           const float* __restrict__ W2) {
    __shared__ float sW1[F_IN * F_HID];   // [k][f]: sW1[k*64+f]
    __shared__ float sb1[F_HID];
    __shared__ float sW2[F_HID];
    for (int t = threadIdx.x; t < F_IN * F_HID; t += blockDim.x) sW1[t] = W1[t];
    for (int t = threadIdx.x; t < F_HID; t += blockDim.x) { sb1[t] = b1[t]; sW2[t] = W2[t]; }
    __syncthreads();

    int i = blockIdx.x * blockDim.x + threadIdx.x;
    if (i >= N_NODES) return;

    float dv = g_dinv[i];
    float dv2 = dv * dv;
    const float4* ac = (const float4*)(g_acc1 + (size_t)i * F_IN);
    const float4* xr = (const float4*)(x + (size_t)i * F_IN);
    float4 A0 = ac[0], A1 = ac[1], X0 = xr[0], X1 = xr[1];
    float a[F_IN];
    a[0] = dv * A0.x + dv2 * X0.x;  a[1] = dv * A0.y + dv2 * X0.y;
    a[2] = dv * A0.z + dv2 * X0.z;  a[3] = dv * A0.w + dv2 * X0.w;
    a[4] = dv * A1.x + dv2 * X1.x;  a[5] = dv * A1.y + dv2 * X1.y;
    a[6] = dv * A1.z + dv2 * X1.z;  a[7] = dv * A1.w + dv2 * X1.w;

    float s = 0.0f;
    #pragma unroll 8
    for (int f = 0; f < F_HID; f++) {
        float acc = sb1[f];
        #pragma unroll
        for (int k = 0; k < F_IN; k++) acc = fmaf(a[k], sW1[k * F_HID + f], acc);
        s += fmaxf(acc, 0.0f) * sW2[f];
    }
    g_sd[i] = dv * s;
}

// 5) layer-2 edge pass, 1 edge/thread: acc2[c] += w * sd[r]
__global__ void k_layer2_edges(const int* __restrict__ ei, const float* __restrict__ w) {
    int e = blockIdx.x * blockDim.x + threadIdx.x;
    if (e >= N_EDGES) return;
    int r = ei[e];
    int c = ei[N_EDGES + e];
    atomicAdd(&g_acc2[c], w[e] * __ldg(&g_sd[r]));
}

// 6) epilogue: out = b2 + dinv * (acc2 + sd)   (plain stores to d_out)
__global__ void k_out(const float* __restrict__ b2, float* __restrict__ out) {
    int i = blockIdx.x * blockDim.x + threadIdx.x;
    if (i < N_NODES) out[i] = b2[0] + g_dinv[i] * (g_acc2[i] + g_sd[i]);
}

extern "C" void kernel_launch(void* const* d_in, const int* in_sizes, int n_in,
                              void* d_out, int out_size) {
    const float* x  = (const float*)d_in[0];
    const int*   ei = (const int*)d_in[1];     // int32 (JAX x64 disabled)
    const float* w  = (const float*)d_in[2];
    const float* W1 = (const float*)d_in[3];
    const float* b1 = (const float*)d_in[4];
    const float* W2 = (const float*)d_in[5];
    const float* b2 = (const float*)d_in[6];
    float* out = (float*)d_out;

    // zero deg via memset graph node (self-loop +1 folded into k_dinv_xs)
    void* deg_ptr = nullptr;
    cudaGetSymbolAddress(&deg_ptr, g_deg);
    cudaMemsetAsync(deg_ptr, 0, N_NODES * sizeof(float));

    const int TB = 256;
    const int gridN = (N_NODES + TB - 1) / TB;
    const int gridE = (N_EDGES + TB - 1) / TB;

    k_deg_acc<<<gridE, TB>>>(ei, w);
    k_dinv_xs<<<gridN, TB>>>(x);
    k_layer1_edges<<<gridE, TB>>>(ei, w);
    k_node_mlp<<<gridN, TB>>>(x, W1, b1, W2);
    k_layer2_edges<<<gridE, TB>>>(ei, w);
    k_out<<<gridN, TB>>>(b2, out);
}

// round 10
// speedup vs baseline: 1.5843x; 1.0647x over previous
#include <cuda_runtime.h>
#include <cuda_fp16.h>
#include <cuda_bf16.h>

#define N_NODES 100000
#define N_EDGES 3200000
#define F_IN 8
#define F_HID 64

// Scratch: __device__ globals (GPU DRAM; allocation-free rule)
__device__ float g_deg[N_NODES];                           // accumulated WITHOUT self-loop
__device__ float g_dinv[N_NODES];
__device__ __align__(16) float g_xs[N_NODES * F_IN];       // dinv[i] * x[i]
__device__ __align__(16) unsigned g_acc1h[N_NODES * 4];    // 8 fp16 accumulators per node (4x half2)
__device__ float g_sd[N_NODES];                            // dinv[i] * s[i]
__device__ float g_acc2[N_NODES];                          // layer-2 accumulator

__device__ __forceinline__ unsigned h2_bits(__half2 h) {
    union { __half2 h; unsigned u; } cvt; cvt.h = h; return cvt.u;
}

// ---------------------------------------------------------------------------
// 1) deg accumulate: deg[col] += w   (deg zeroed by memset; self-loop +1 in dinv)
__global__ void k_deg_acc(const int* __restrict__ ei, const float* __restrict__ w) {
    int e = blockIdx.x * blockDim.x + threadIdx.x;
    if (e >= N_EDGES) return;
    atomicAdd(&g_deg[ei[N_EDGES + e]], w[e]);
}

// 2) dinv = rsqrt(1 + deg); xs = dinv*x; zero acc1h & acc2 (fused init)
__global__ void k_dinv_xs(const float* __restrict__ x) {
    int i = blockIdx.x * blockDim.x + threadIdx.x;
    if (i >= N_NODES) return;
    float dv = rsqrtf(1.0f + g_deg[i]);     // +1 = self-loop weight
    g_dinv[i] = dv;
    const float4* xr = (const float4*)(x + (size_t)i * F_IN);
    float4 a = xr[0], b = xr[1];
    float4* o = (float4*)(g_xs + (size_t)i * F_IN);
    o[0] = make_float4(a.x * dv, a.y * dv, a.z * dv, a.w * dv);
    o[1] = make_float4(b.x * dv, b.y * dv, b.z * dv, b.w * dv);
    ((uint4*)g_acc1h)[i] = make_uint4(0u, 0u, 0u, 0u);
    g_acc2[i] = 0.0f;
}

// fire-and-forget packed-half reduction: 8 halves in one 16B RED (sm_103a)
__device__ __forceinline__ void red_add_v4_f16x2(unsigned* p, unsigned h0, unsigned h1,
                                                 unsigned h2, unsigned h3) {
    asm volatile("red.global.add.noftz.v4.f16x2 [%0], {%1,%2,%3,%4};"
                 :: "l"(p), "r"(h0), "r"(h1), "r"(h2), "r"(h3) : "memory");
}

// 3) layer-1 edge pass, 1 edge/thread: acc1[c] += w * xs[r]  (1 RED + 1 gather)
__global__ void k_layer1_edges(const int* __restrict__ ei, const float* __restrict__ w) {
    int e = blockIdx.x * blockDim.x + threadIdx.x;
    if (e >= N_EDGES) return;
    int r = ei[e];
    int c = ei[N_EDGES + e];
    float we = w[e];
    const float4* xr = (const float4*)(g_xs + (size_t)r * F_IN);
    float4 a = __ldg(xr);
    float4 b = __ldg(xr + 1);
    __half2 h0 = __floats2half2_rn(we * a.x, we * a.y);
    __half2 h1 = __floats2half2_rn(we * a.z, we * a.w);
    __half2 h2 = __floats2half2_rn(we * b.x, we * b.y);
    __half2 h3 = __floats2half2_rn(we * b.z, we * b.w);
    red_add_v4_f16x2(g_acc1h + (size_t)c * 4,
                     h2_bits(h0), h2_bits(h1), h2_bits(h2), h2_bits(h3));
}

// 4) node MLP, 2 threads/node (f-split): a = dinv*acc1 + dinv^2*x ;
//    s = relu(a@W1+b1)@W2 ; sd = dinv*s
__global__ void k_node_mlp(const float* __restrict__ x,
                           const float* __restrict__ W1,
                           const float* __restrict__ b1,
                           const float* __restrict__ W2) {
    __shared__ float sW1[F_IN * F_HID];   // [k][f]: sW1[k*64+f]
    __shared__ float sb1[F_HID];
    __shared__ float sW2[F_HID];
    for (int t = threadIdx.x; t < F_IN * F_HID; t += blockDim.x) sW1[t] = W1[t];
    for (int t = threadIdx.x; t < F_HID; t += blockDim.x) { sb1[t] = b1[t]; sW2[t] = W2[t]; }
    __syncthreads();

    int gid = blockIdx.x * blockDim.x + threadIdx.x;
    int i = gid >> 1;
    int half_id = gid & 1;
    if (i >= N_NODES) return;

    float dv = g_dinv[i];
    float dv2 = dv * dv;
    uint4 u = __ldg((const uint4*)(g_acc1h + (size_t)i * 4));
    float2 f0 = __half22float2(*(__half2*)&u.x);
    float2 f1 = __half22float2(*(__half2*)&u.y);
    float2 f2 = __half22float2(*(__half2*)&u.z);
    float2 f3 = __half22float2(*(__half2*)&u.w);
    const float4* xr = (const float4*)(x + (size_t)i * F_IN);
    float4 X0 = __ldg(xr), X1 = __ldg(xr + 1);
    float a[F_IN];
    a[0] = dv * f0.x + dv2 * X0.x;  a[1] = dv * f0.y + dv2 * X0.y;
    a[2] = dv * f1.x + dv2 * X0.z;  a[3] = dv * f1.y + dv2 * X0.w;
    a[4] = dv * f2.x + dv2 * X1.x;  a[5] = dv * f2.y + dv2 * X1.y;
    a[6] = dv * f3.x + dv2 * X1.z;  a[7] = dv * f3.y + dv2 * X1.w;

    float s = 0.0f;
    int fbase = half_id * (F_HID / 2);
    #pragma unroll 8
    for (int f = 0; f < F_HID / 2; f++) {
        int ff = fbase + f;
        float acc = sb1[ff];
        #pragma unroll
        for (int k = 0; k < F_IN; k++) acc = fmaf(a[k], sW1[k * F_HID + ff], acc);
        s += fmaxf(acc, 0.0f) * sW2[ff];
    }
    s += __shfl_xor_sync(0xffffffffu, s, 1);
    if (half_id == 0) g_sd[i] = dv * s;
}

// 5) layer-2 edge pass, 1 edge/thread: acc2[c] += w * sd[r]
__global__ void k_layer2_edges(const int* __restrict__ ei, const float* __restrict__ w) {
    int e = blockIdx.x * blockDim.x + threadIdx.x;
    if (e >= N_EDGES) return;
    int r = ei[e];
    int c = ei[N_EDGES + e];
    atomicAdd(&g_acc2[c], w[e] * __ldg(&g_sd[r]));
}

// 6) epilogue: out = b2 + dinv * (acc2 + sd)   (plain stores to d_out)
__global__ void k_out(const float* __restrict__ b2, float* __restrict__ out) {
    int i = blockIdx.x * blockDim.x + threadIdx.x;
    if (i < N_NODES) out[i] = b2[0] + g_dinv[i] * (g_acc2[i] + g_sd[i]);
}

extern "C" void kernel_launch(void* const* d_in, const int* in_sizes, int n_in,
                              void* d_out, int out_size) {
    const float* x  = (const float*)d_in[0];
    const int*   ei = (const int*)d_in[1];     // int32 (JAX x64 disabled)
    const float* w  = (const float*)d_in[2];
    const float* W1 = (const float*)d_in[3];
    const float* b1 = (const float*)d_in[4];
    const float* W2 = (const float*)d_in[5];
    const float* b2 = (const float*)d_in[6];
    float* out = (float*)d_out;

    // zero deg via memset graph node (self-loop +1 folded into k_dinv_xs)
    void* deg_ptr = nullptr;
    cudaGetSymbolAddress(&deg_ptr, g_deg);
    cudaMemsetAsync(deg_ptr, 0, N_NODES * sizeof(float));

    const int TB = 256;
    const int gridN  = (N_NODES + TB - 1) / TB;
    const int gridN2 = (2 * N_NODES + TB - 1) / TB;
    const int gridE  = (N_EDGES + TB - 1) / TB;

    k_deg_acc<<<gridE, TB>>>(ei, w);
    k_dinv_xs<<<gridN, TB>>>(x);
    k_layer1_edges<<<gridE, TB>>>(ei, w);
    k_node_mlp<<<gridN2, TB>>>(x, W1, b1, W2);
    k_layer2_edges<<<gridE, TB>>>(ei, w);
    k_out<<<gridN, TB>>>(b2, out);
}

// round 11
// speedup vs baseline: 1.6581x; 1.0466x over previous
#include <cuda_runtime.h>
#include <cuda_fp16.h>
#include <cuda_bf16.h>

#define N_NODES 100000
#define N_EDGES 3200000
#define F_IN 8
#define F_HID 64

// Scratch: __device__ globals (GPU DRAM; allocation-free rule)
__device__ float g_deg[N_NODES];                           // accumulated WITHOUT self-loop
__device__ float g_dinv[N_NODES];
__device__ __align__(16) float g_xs[N_NODES * F_IN];       // dinv[i] * x[i]
__device__ __align__(16) unsigned g_acc1h[N_NODES * 4];    // 8 fp16 accumulators/node (4x half2)
__device__ float g_sd[N_NODES];                            // dinv[i] * s[i]
__device__ float g_acc2[N_NODES];                          // layer-2 accumulator

__device__ __forceinline__ unsigned h2_bits(__half2 h) {
    union { __half2 h; unsigned u; } cvt; cvt.h = h; return cvt.u;
}

// packed f32x2 helpers (Blackwell dual-issue FMA: FFMA2 only via PTX fma.rn.f32x2)
#define PACK_F32X2(out, lo, hi) \
    asm("mov.b64 %0, {%1, %2};" : "=l"(out) : "f"(lo), "f"(hi))
#define UNPACK_F32X2(lo, hi, in) \
    asm("mov.b64 {%0, %1}, %2;" : "=f"(lo), "=f"(hi) : "l"(in))
#define FMA_F32X2(d, a, b, c) \
    asm("fma.rn.f32x2 %0, %1, %2, %3;" : "=l"(d) : "l"(a), "l"(b), "l"(c))

// ---------------------------------------------------------------------------
// 1) deg accumulate: deg[col] += w   (deg zeroed by memset; self-loop +1 in dinv)
__global__ void k_deg_acc(const int* __restrict__ ei, const float* __restrict__ w) {
    int e = blockIdx.x * blockDim.x + threadIdx.x;
    if (e >= N_EDGES) return;
    atomicAdd(&g_deg[ei[N_EDGES + e]], w[e]);
}

// 2) dinv = rsqrt(1 + deg); xs = dinv*x; zero acc1h & acc2 (fused init)
__global__ void k_dinv_xs(const float* __restrict__ x) {
    int i = blockIdx.x * blockDim.x + threadIdx.x;
    if (i >= N_NODES) return;
    float dv = rsqrtf(1.0f + g_deg[i]);     // +1 = self-loop weight
    g_dinv[i] = dv;
    const float4* xr = (const float4*)(x + (size_t)i * F_IN);
    float4 a = xr[0], b = xr[1];
    float4* o = (float4*)(g_xs + (size_t)i * F_IN);
    o[0] = make_float4(a.x * dv, a.y * dv, a.z * dv, a.w * dv);
    o[1] = make_float4(b.x * dv, b.y * dv, b.z * dv, b.w * dv);
    ((uint4*)g_acc1h)[i] = make_uint4(0u, 0u, 0u, 0u);
    g_acc2[i] = 0.0f;
}

// fire-and-forget packed-half reduction: 8 halves in one 16B RED (sm_103a)
__device__ __forceinline__ void red_add_v4_f16x2(unsigned* p, unsigned h0, unsigned h1,
                                                 unsigned h2, unsigned h3) {
    asm volatile("red.global.add.noftz.v4.f16x2 [%0], {%1,%2,%3,%4};"
                 :: "l"(p), "r"(h0), "r"(h1), "r"(h2), "r"(h3) : "memory");
}

// 3) layer-1 edge pass, 1 edge/thread: acc1[c] += w * xs[r]  (1 RED + 1 gather)
__global__ void k_layer1_edges(const int* __restrict__ ei, const float* __restrict__ w) {
    int e = blockIdx.x * blockDim.x + threadIdx.x;
    if (e >= N_EDGES) return;
    int r = ei[e];
    int c = ei[N_EDGES + e];
    float we = w[e];
    const float4* xr = (const float4*)(g_xs + (size_t)r * F_IN);
    float4 a = __ldg(xr);
    float4 b = __ldg(xr + 1);
    __half2 h0 = __floats2half2_rn(we * a.x, we * a.y);
    __half2 h1 = __floats2half2_rn(we * a.z, we * a.w);
    __half2 h2 = __floats2half2_rn(we * b.x, we * b.y);
    __half2 h3 = __floats2half2_rn(we * b.z, we * b.w);
    red_add_v4_f16x2(g_acc1h + (size_t)c * 4,
                     h2_bits(h0), h2_bits(h1), h2_bits(h2), h2_bits(h3));
}

// 4) node MLP, 1 thread/node, f-pairs via fma.rn.f32x2:
//    a = dinv*acc1 + dinv^2*x ; s = relu(a@W1+b1)@W2 ; sd = dinv*s
__global__ void k_node_mlp(const float* __restrict__ x,
                           const float* __restrict__ W1,
                           const float* __restrict__ b1,
                           const float* __restrict__ W2) {
    __shared__ unsigned long long sW1p[F_IN * F_HID / 2];  // [k][fp]: packed (W1[k][2fp], W1[k][2fp+1])
    __shared__ float2 sb1p[F_HID / 2];
    __shared__ float  sW2[F_HID];
    for (int t = threadIdx.x; t < F_IN * F_HID / 2; t += blockDim.x) {
        float2 v = ((const float2*)W1)[t];   // W1 row-major [8][64]: adjacent f contiguous
        union { float2 f; unsigned long long u; } cvt; cvt.f = v;
        sW1p[t] = cvt.u;
    }
    for (int t = threadIdx.x; t < F_HID / 2; t += blockDim.x) sb1p[t] = ((const float2*)b1)[t];
    for (int t = threadIdx.x; t < F_HID; t += blockDim.x) sW2[t] = W2[t];
    __syncthreads();

    int i = blockIdx.x * blockDim.x + threadIdx.x;
    if (i >= N_NODES) return;

    float dv = g_dinv[i];
    float dv2 = dv * dv;
    uint4 u = __ldg((const uint4*)(g_acc1h + (size_t)i * 4));
    float2 f0 = __half22float2(*(__half2*)&u.x);
    float2 f1 = __half22float2(*(__half2*)&u.y);
    float2 f2 = __half22float2(*(__half2*)&u.z);
    float2 f3 = __half22float2(*(__half2*)&u.w);
    const float4* xr = (const float4*)(x + (size_t)i * F_IN);
    float4 X0 = __ldg(xr), X1 = __ldg(xr + 1);
    float a[F_IN];
    a[0] = dv * f0.x + dv2 * X0.x;  a[1] = dv * f0.y + dv2 * X0.y;
    a[2] = dv * f1.x + dv2 * X0.z;  a[3] = dv * f1.y + dv2 * X0.w;
    a[4] = dv * f2.x + dv2 * X1.x;  a[5] = dv * f2.y + dv2 * X1.y;
    a[6] = dv * f3.x + dv2 * X1.z;  a[7] = dv * f3.y + dv2 * X1.w;

    // broadcast-pack each a[k] into both halves once
    unsigned long long apk[F_IN];
    #pragma unroll
    for (int k = 0; k < F_IN; k++) PACK_F32X2(apk[k], a[k], a[k]);

    float s = 0.0f;
    #pragma unroll 4
    for (int fp = 0; fp < F_HID / 2; fp++) {
        float2 bb = sb1p[fp];
        unsigned long long acc;
        PACK_F32X2(acc, bb.x, bb.y);
        #pragma unroll
        for (int k = 0; k < F_IN; k++)
            FMA_F32X2(acc, apk[k], sW1p[k * (F_HID / 2) + fp], acc);
        float lo, hi;
        UNPACK_F32X2(lo, hi, acc);
        s = fmaf(fmaxf(lo, 0.0f), sW2[2 * fp],     s);
        s = fmaf(fmaxf(hi, 0.0f), sW2[2 * fp + 1], s);
    }
    g_sd[i] = dv * s;
}

// 5) layer-2 edge pass, 1 edge/thread: acc2[c] += w * sd[r]
__global__ void k_layer2_edges(const int* __restrict__ ei, const float* __restrict__ w) {
    int e = blockIdx.x * blockDim.x + threadIdx.x;
    if (e >= N_EDGES) return;
    int r = ei[e];
    int c = ei[N_EDGES + e];
    atomicAdd(&g_acc2[c], w[e] * __ldg(&g_sd[r]));
}

// 6) epilogue: out = b2 + dinv * (acc2 + sd)   (plain stores to d_out)
__global__ void k_out(const float* __restrict__ b2, float* __restrict__ out) {
    int i = blockIdx.x * blockDim.x + threadIdx.x;
    if (i < N_NODES) out[i] = b2[0] + g_dinv[i] * (g_acc2[i] + g_sd[i]);
}

extern "C" void kernel_launch(void* const* d_in, const int* in_sizes, int n_in,
                              void* d_out, int out_size) {
    const float* x  = (const float*)d_in[0];
    const int*   ei = (const int*)d_in[1];     // int32 (JAX x64 disabled)
    const float* w  = (const float*)d_in[2];
    const float* W1 = (const float*)d_in[3];
    const float* b1 = (const float*)d_in[4];
    const float* W2 = (const float*)d_in[5];
    const float* b2 = (const float*)d_in[6];
    float* out = (float*)d_out;

    // zero deg via memset graph node (self-loop +1 folded into k_dinv_xs)
    void* deg_ptr = nullptr;
    cudaGetSymbolAddress(&deg_ptr, g_deg);
    cudaMemsetAsync(deg_ptr, 0, N_NODES * sizeof(float));

    const int TB = 256;
    const int gridN = (N_NODES + TB - 1) / TB;
    const int gridE = (N_EDGES + TB - 1) / TB;

    k_deg_acc<<<gridE, TB>>>(ei, w);
    k_dinv_xs<<<gridN, TB>>>(x);
    k_layer1_edges<<<gridE, TB>>>(ei, w);
    k_node_mlp<<<gridN, TB>>>(x, W1, b1, W2);
    k_layer2_edges<<<gridE, TB>>>(ei, w);
    k_out<<<gridN, TB>>>(b2, out);
}

// round 12
// speedup vs baseline: 1.7305x; 1.0436x over previous
#include <cuda_runtime.h>
#include <cuda_fp16.h>
#include <cuda_bf16.h>

#define N_NODES 100000
#define N_EDGES 3200000
#define F_IN 8
#define F_HID 64

// Scratch: __device__ globals (GPU DRAM; allocation-free rule)
__device__ float g_deg[N_NODES];                           // accumulated WITHOUT self-loop
__device__ float g_dinv[N_NODES];
__device__ __align__(16) unsigned g_xsh[N_NODES * 4];      // dinv[i]*x[i] as 8 fp16 (4x half2)
__device__ __align__(16) unsigned g_acc1h[N_NODES * 4];    // 8 fp16 accumulators/node (4x half2)
__device__ float g_sd[N_NODES];                            // dinv[i] * s[i]
__device__ float g_acc2[N_NODES];                          // layer-2 accumulator

__device__ __forceinline__ unsigned h2_bits(__half2 h) {
    union { __half2 h; unsigned u; } cvt; cvt.h = h; return cvt.u;
}
__device__ __forceinline__ __half2 bits_h2(unsigned u) {
    union { unsigned u; __half2 h; } cvt; cvt.u = u; return cvt.h;
}

// packed f32x2 helpers (Blackwell dual-issue FMA: FFMA2 only via PTX fma.rn.f32x2)
#define PACK_F32X2(out, lo, hi) \
    asm("mov.b64 %0, {%1, %2};" : "=l"(out) : "f"(lo), "f"(hi))
#define UNPACK_F32X2(lo, hi, in) \
    asm("mov.b64 {%0, %1}, %2;" : "=f"(lo), "=f"(hi) : "l"(in))
#define FMA_F32X2(d, a, b, c) \
    asm("fma.rn.f32x2 %0, %1, %2, %3;" : "=l"(d) : "l"(a), "l"(b), "l"(c))

// ---------------------------------------------------------------------------
// 1) deg accumulate: deg[col] += w   (deg zeroed by memset; self-loop +1 in dinv)
__global__ void k_deg_acc(const int* __restrict__ ei, const float* __restrict__ w) {
    int e = blockIdx.x * blockDim.x + threadIdx.x;
    if (e >= N_EDGES) return;
    atomicAdd(&g_deg[ei[N_EDGES + e]], w[e]);
}

// 2) dinv = rsqrt(1 + deg); xsh = fp16(dinv*x); zero acc1h & acc2 (fused init)
__global__ void k_dinv_xs(const float* __restrict__ x) {
    int i = blockIdx.x * blockDim.x + threadIdx.x;
    if (i >= N_NODES) return;
    float dv = rsqrtf(1.0f + g_deg[i]);     // +1 = self-loop weight
    g_dinv[i] = dv;
    const float4* xr = (const float4*)(x + (size_t)i * F_IN);
    float4 a = xr[0], b = xr[1];
    uint4 pk;
    pk.x = h2_bits(__floats2half2_rn(a.x * dv, a.y * dv));
    pk.y = h2_bits(__floats2half2_rn(a.z * dv, a.w * dv));
    pk.z = h2_bits(__floats2half2_rn(b.x * dv, b.y * dv));
    pk.w = h2_bits(__floats2half2_rn(b.z * dv, b.w * dv));
    ((uint4*)g_xsh)[i] = pk;
    ((uint4*)g_acc1h)[i] = make_uint4(0u, 0u, 0u, 0u);
    g_acc2[i] = 0.0f;
}

// fire-and-forget packed-half reduction: 8 halves in one 16B RED (sm_103a)
__device__ __forceinline__ void red_add_v4_f16x2(unsigned* p, unsigned h0, unsigned h1,
                                                 unsigned h2, unsigned h3) {
    asm volatile("red.global.add.noftz.v4.f16x2 [%0], {%1,%2,%3,%4};"
                 :: "l"(p), "r"(h0), "r"(h1), "r"(h2), "r"(h3) : "memory");
}

// 3) layer-1 edge pass, 1 edge/thread: acc1[c] += w * xs[r]
//    Now 1 LDG.128 gather (fp16 xs) + 1 RED.128; multiply kept in fp32 for precision.
__global__ void k_layer1_edges(const int* __restrict__ ei, const float* __restrict__ w) {
    int e = blockIdx.x * blockDim.x + threadIdx.x;
    if (e >= N_EDGES) return;
    int r = ei[e];
    int c = ei[N_EDGES + e];
    float we = w[e];
    uint4 u = __ldg((const uint4*)(g_xsh + (size_t)r * 4));
    float2 p0 = __half22float2(bits_h2(u.x));
    float2 p1 = __half22float2(bits_h2(u.y));
    float2 p2 = __half22float2(bits_h2(u.z));
    float2 p3 = __half22float2(bits_h2(u.w));
    unsigned h0 = h2_bits(__floats2half2_rn(we * p0.x, we * p0.y));
    unsigned h1 = h2_bits(__floats2half2_rn(we * p1.x, we * p1.y));
    unsigned h2 = h2_bits(__floats2half2_rn(we * p2.x, we * p2.y));
    unsigned h3 = h2_bits(__floats2half2_rn(we * p3.x, we * p3.y));
    red_add_v4_f16x2(g_acc1h + (size_t)c * 4, h0, h1, h2, h3);
}

// 4) node MLP, 1 thread/node, f-pairs via fma.rn.f32x2:
//    a = dinv*acc1 + dinv^2*x ; s = relu(a@W1+b1)@W2 ; sd = dinv*s
__global__ void k_node_mlp(const float* __restrict__ x,
                           const float* __restrict__ W1,
                           const float* __restrict__ b1,
                           const float* __restrict__ W2) {
    __shared__ unsigned long long sW1p[F_IN * F_HID / 2];  // [k][fp]: packed (W1[k][2fp], W1[k][2fp+1])
    __shared__ float2 sb1p[F_HID / 2];
    __shared__ float  sW2[F_HID];
    for (int t = threadIdx.x; t < F_IN * F_HID / 2; t += blockDim.x) {
        float2 v = ((const float2*)W1)[t];   // W1 row-major [8][64]: adjacent f contiguous
        union { float2 f; unsigned long long u; } cvt; cvt.f = v;
        sW1p[t] = cvt.u;
    }
    for (int t = threadIdx.x; t < F_HID / 2; t += blockDim.x) sb1p[t] = ((const float2*)b1)[t];
    for (int t = threadIdx.x; t < F_HID; t += blockDim.x) sW2[t] = W2[t];
    __syncthreads();

    int i = blockIdx.x * blockDim.x + threadIdx.x;
    if (i >= N_NODES) return;

    float dv = g_dinv[i];
    float dv2 = dv * dv;
    uint4 u = __ldg((const uint4*)(g_acc1h + (size_t)i * 4));
    float2 f0 = __half22float2(bits_h2(u.x));
    float2 f1 = __half22float2(bits_h2(u.y));
    float2 f2 = __half22float2(bits_h2(u.z));
    float2 f3 = __half22float2(bits_h2(u.w));
    const float4* xr = (const float4*)(x + (size_t)i * F_IN);
    float4 X0 = __ldg(xr), X1 = __ldg(xr + 1);
    float a[F_IN];
    a[0] = dv * f0.x + dv2 * X0.x;  a[1] = dv * f0.y + dv2 * X0.y;
    a[2] = dv * f1.x + dv2 * X0.z;  a[3] = dv * f1.y + dv2 * X0.w;
    a[4] = dv * f2.x + dv2 * X1.x;  a[5] = dv * f2.y + dv2 * X1.y;
    a[6] = dv * f3.x + dv2 * X1.z;  a[7] = dv * f3.y + dv2 * X1.w;

    // broadcast-pack each a[k] into both halves once
    unsigned long long apk[F_IN];
    #pragma unroll
    for (int k = 0; k < F_IN; k++) PACK_F32X2(apk[k], a[k], a[k]);

    float s = 0.0f;
    #pragma unroll 4
    for (int fp = 0; fp < F_HID / 2; fp++) {
        float2 bb = sb1p[fp];
        unsigned long long acc;
        PACK_F32X2(acc, bb.x, bb.y);
        #pragma unroll
        for (int k = 0; k < F_IN; k++)
            FMA_F32X2(acc, apk[k], sW1p[k * (F_HID / 2) + fp], acc);
        float lo, hi;
        UNPACK_F32X2(lo, hi, acc);
        s = fmaf(fmaxf(lo, 0.0f), sW2[2 * fp],     s);
        s = fmaf(fmaxf(hi, 0.0f), sW2[2 * fp + 1], s);
    }
    g_sd[i] = dv * s;
}

// 5) layer-2 edge pass, 1 edge/thread: acc2[c] += w * sd[r]
__global__ void k_layer2_edges(const int* __restrict__ ei, const float* __restrict__ w) {
    int e = blockIdx.x * blockDim.x + threadIdx.x;
    if (e >= N_EDGES) return;
    int r = ei[e];
    int c = ei[N_EDGES + e];
    atomicAdd(&g_acc2[c], w[e] * __ldg(&g_sd[r]));
}

// 6) epilogue: out = b2 + dinv * (acc2 + sd)   (plain stores to d_out)
__global__ void k_out(const float* __restrict__ b2, float* __restrict__ out) {
    int i = blockIdx.x * blockDim.x + threadIdx.x;
    if (i < N_NODES) out[i] = b2[0] + g_dinv[i] * (g_acc2[i] + g_sd[i]);
}

extern "C" void kernel_launch(void* const* d_in, const int* in_sizes, int n_in,
                              void* d_out, int out_size) {
    const float* x  = (const float*)d_in[0];
    const int*   ei = (const int*)d_in[1];     // int32 (JAX x64 disabled)
    const float* w  = (const float*)d_in[2];
    const float* W1 = (const float*)d_in[3];
    const float* b1 = (const float*)d_in[4];
    const float* W2 = (const float*)d_in[5];
    const float* b2 = (const float*)d_in[6];
    float* out = (float*)d_out;

    // zero deg via memset graph node (self-loop +1 folded into k_dinv_xs)
    void* deg_ptr = nullptr;
    cudaGetSymbolAddress(&deg_ptr, g_deg);
    cudaMemsetAsync(deg_ptr, 0, N_NODES * sizeof(float));

    const int TB = 256;
    const int gridN = (N_NODES + TB - 1) / TB;
    const int gridE = (N_EDGES + TB - 1) / TB;

    k_deg_acc<<<gridE, TB>>>(ei, w);
    k_dinv_xs<<<gridN, TB>>>(x);
    k_layer1_edges<<<gridE, TB>>>(ei, w);
    k_node_mlp<<<gridN, TB>>>(x, W1, b1, W2);
    k_layer2_edges<<<gridE, TB>>>(ei, w);
    k_out<<<gridN, TB>>>(b2, out);
}